// round 1
// baseline (speedup 1.0000x reference)
#include <cuda_runtime.h>
#include <math.h>

#define BB 8
#define DD 256
#define NN 2048
#define NH 4
#define HD 64

// Scratch (allocation-free rule: __device__ globals)
__device__ float g_q[BB*DD*NN];
__device__ float g_k[BB*DD*NN];
__device__ float g_v[BB*DD*NN];
__device__ float g_x[BB*DD*NN];

// ---------------------------------------------------------------------------
// Projection GEMM: Y[b,o,n] = bias[o] + sum_i W[o,i] * X[b,i,n]
// Tile: 64(o) x 64(n), K-chunks of 16. 256 threads, 4x4 micro-tile per thread.
// ---------------------------------------------------------------------------
__global__ __launch_bounds__(256) void proj_kernel(
    const float* __restrict__ W, const float* __restrict__ bias,
    const float* __restrict__ X, float* __restrict__ Y)
{
    __shared__ float sW[16][65];  // [kk][oo]
    __shared__ float sX[16][65];  // [kk][nn]

    const int b  = blockIdx.z;
    const int o0 = blockIdx.y * 64;
    const int n0 = blockIdx.x * 64;
    const int tx = threadIdx.x & 15;
    const int ty = threadIdx.x >> 4;

    const float* Xb = X + (size_t)b * DD * NN;
    float acc[4][4];
#pragma unroll
    for (int i = 0; i < 4; i++)
#pragma unroll
        for (int j = 0; j < 4; j++) acc[i][j] = 0.f;

    for (int k0 = 0; k0 < DD; k0 += 16) {
#pragma unroll
        for (int i = 0; i < 4; i++) {
            int idx = threadIdx.x + i * 256;      // 0..1023
            int oo = idx >> 4, kk = idx & 15;
            sW[kk][oo] = W[(o0 + oo) * DD + k0 + kk];
        }
#pragma unroll
        for (int i = 0; i < 4; i++) {
            int idx = threadIdx.x + i * 256;
            int kk = idx >> 6, nn = idx & 63;
            sX[kk][nn] = Xb[(k0 + kk) * NN + n0 + nn];
        }
        __syncthreads();
#pragma unroll
        for (int kk = 0; kk < 16; kk++) {
            float wr[4], xr[4];
#pragma unroll
            for (int i = 0; i < 4; i++) wr[i] = sW[kk][ty * 4 + i];
#pragma unroll
            for (int j = 0; j < 4; j++) xr[j] = sX[kk][tx * 4 + j];
#pragma unroll
            for (int i = 0; i < 4; i++)
#pragma unroll
                for (int j = 0; j < 4; j++) acc[i][j] += wr[i] * xr[j];
        }
        __syncthreads();
    }

    float* Yb = Y + (size_t)b * DD * NN;
#pragma unroll
    for (int i = 0; i < 4; i++) {
        int o = o0 + ty * 4 + i;
        float bv = bias[o];
#pragma unroll
        for (int j = 0; j < 4; j++)
            Yb[o * NN + n0 + tx * 4 + j] = acc[i][j] + bv;
    }
}

// ---------------------------------------------------------------------------
// Flash-style attention, fp32.
// Channel mapping from reshape(B, d, H, N): channel c = dd*NH + h.
// Block = (b, h, 64-query tile). 256 threads: thread t -> query row t/4,
// quarter t%4 (handles 16 keys of S and 16 dims of O).
// ---------------------------------------------------------------------------
__global__ __launch_bounds__(256) void attn_kernel(const int* __restrict__ mask)
{
    extern __shared__ float sm[];
    float* sQ = sm;               // 64 x 65   [n][dd]
    float* sK = sQ + 64 * 65;     // 64 x 65   [m][dd]
    float* sV = sK + 64 * 65;     // 64 x 65   [m][dd]
    float* sP = sV + 64 * 65;     // 64 x 65   [n][m]
    __shared__ int smask[64];

    const int b  = blockIdx.z;
    const int h  = blockIdx.y;
    const int q0 = blockIdx.x * 64;
    const int t  = threadIdx.x;
    const int qr = t >> 2;   // query row in tile
    const int qq = t & 3;    // quarter

    const float* Qb = g_q + (size_t)b * DD * NN;
    const float* Kb = g_k + (size_t)b * DD * NN;
    const float* Vb = g_v + (size_t)b * DD * NN;
    const int*   mb = mask + (size_t)b * NN;

    // Load Q tile: sQ[n][dd] = Qb[(dd*NH+h)*NN + q0+n]
#pragma unroll
    for (int i = 0; i < 16; i++) {
        int idx = t + i * 256;
        int dd = idx >> 6, n = idx & 63;
        sQ[n * 65 + dd] = Qb[(dd * NH + h) * NN + q0 + n];
    }
    const int qmask = mb[q0 + qr];

    float m_old = -INFINITY, l = 0.f;
    float acc[16];
#pragma unroll
    for (int i = 0; i < 16; i++) acc[i] = 0.f;

    for (int k0 = 0; k0 < NN; k0 += 64) {
        __syncthreads();  // protect sK/sV/sP reuse (and sQ on first iter)
#pragma unroll
        for (int i = 0; i < 16; i++) {
            int idx = t + i * 256;
            int dd = idx >> 6, m = idx & 63;
            int c = (dd * NH + h) * NN + k0 + m;
            sK[m * 65 + dd] = Kb[c];
            sV[m * 65 + dd] = Vb[c];
        }
        if (t < 64) smask[t] = mb[k0 + t];
        __syncthreads();

        // S = Q K^T / 8 for this thread's 16 keys
        float s[16];
#pragma unroll
        for (int j = 0; j < 16; j++) s[j] = 0.f;
        for (int dd = 0; dd < 64; dd++) {
            float qv = sQ[qr * 65 + dd];
#pragma unroll
            for (int j = 0; j < 16; j++)
                s[j] += qv * sK[(qq * 16 + j) * 65 + dd];
        }
        float tmax = -INFINITY;
#pragma unroll
        for (int j = 0; j < 16; j++) {
            s[j] *= 0.125f;
            if (qmask == 0 || smask[qq * 16 + j] == 0) s[j] = -1e9f;
            tmax = fmaxf(tmax, s[j]);
        }
        // reduce max over the 4 threads of this query (lanes grouped by 4)
        tmax = fmaxf(tmax, __shfl_xor_sync(0xffffffffu, tmax, 1));
        tmax = fmaxf(tmax, __shfl_xor_sync(0xffffffffu, tmax, 2));
        float m_new = fmaxf(m_old, tmax);
        float corr  = __expf(m_old - m_new);   // m_old=-inf first iter -> 0
        float lsum = 0.f;
#pragma unroll
        for (int j = 0; j < 16; j++) {
            s[j] = __expf(s[j] - m_new);
            lsum += s[j];
        }
        lsum += __shfl_xor_sync(0xffffffffu, lsum, 1);
        lsum += __shfl_xor_sync(0xffffffffu, lsum, 2);
        l = l * corr + lsum;
        m_old = m_new;
#pragma unroll
        for (int i = 0; i < 16; i++) acc[i] *= corr;

        // stage P through smem so all 4 threads of a query see the full row
#pragma unroll
        for (int j = 0; j < 16; j++) sP[qr * 65 + qq * 16 + j] = s[j];
        __syncthreads();

        // O[n][dd] += sum_m P[n][m] * V[m][dd]
        for (int m = 0; m < 64; m++) {
            float p = sP[qr * 65 + m];
#pragma unroll
            for (int i = 0; i < 16; i++)
                acc[i] += p * sV[m * 65 + qq * 16 + i];
        }
    }

    // x[b, dd*NH+h, q0+qr] = acc/l
    const float inv = 1.f / l;
    float* Xb = g_x + (size_t)b * DD * NN;
#pragma unroll
    for (int i = 0; i < 16; i++) {
        int dd = qq * 16 + i;
        Xb[(dd * NH + h) * NN + q0 + qr] = acc[i] * inv;
    }
}

// ---------------------------------------------------------------------------
extern "C" void kernel_launch(void* const* d_in, const int* in_sizes, int n_in,
                              void* d_out, int out_size)
{
    const float* query = (const float*)d_in[0];
    const float* key_  = (const float*)d_in[1];
    const float* value = (const float*)d_in[2];
    const int*   mask  = (const int*)  d_in[3];
    const float* Wq = (const float*)d_in[4];
    const float* bq = (const float*)d_in[5];
    const float* Wk = (const float*)d_in[6];
    const float* bk = (const float*)d_in[7];
    const float* Wv = (const float*)d_in[8];
    const float* bv = (const float*)d_in[9];
    const float* Wm = (const float*)d_in[10];
    const float* bm = (const float*)d_in[11];
    float* out = (float*)d_out;

    float *q, *k, *v, *x;
    cudaGetSymbolAddress((void**)&q, g_q);
    cudaGetSymbolAddress((void**)&k, g_k);
    cudaGetSymbolAddress((void**)&v, g_v);
    cudaGetSymbolAddress((void**)&x, g_x);

    dim3 pgrid(NN / 64, DD / 64, BB);
    proj_kernel<<<pgrid, 256>>>(Wq, bq, query, q);
    proj_kernel<<<pgrid, 256>>>(Wk, bk, key_,  k);
    proj_kernel<<<pgrid, 256>>>(Wv, bv, value, v);

    size_t smem = (size_t)4 * 64 * 65 * sizeof(float);  // 66,560 B
    static int attr_set = 0;
    cudaFuncSetAttribute(attn_kernel,
                         cudaFuncAttributeMaxDynamicSharedMemorySize, (int)smem);
    (void)attr_set;

    dim3 agrid(NN / 64, NH, BB);
    attn_kernel<<<agrid, 256, smem>>>(mask);

    proj_kernel<<<pgrid, 256>>>(Wm, bm, x, out);
}

// round 2
// speedup vs baseline: 3.4434x; 3.4434x over previous
#include <cuda_runtime.h>
#include <math.h>

#define BB 8
#define DD 256
#define NN 2048
#define NH 4
#define HD 64
#define PAD 68

typedef unsigned long long u64;

// Scratch (allocation-free rule: __device__ globals)
__device__ float g_q[BB*DD*NN];
__device__ float g_k[BB*DD*NN];
__device__ float g_v[BB*DD*NN];
__device__ float g_x[BB*DD*NN];

// ---------------- packed f32x2 helpers (Blackwell) ----------------
__device__ __forceinline__ void ffma2(u64& d, u64 a, u64 b) {
    asm("fma.rn.f32x2 %0, %1, %2, %3;" : "=l"(d) : "l"(a), "l"(b), "l"(d));
}
__device__ __forceinline__ u64 mul2(u64 a, u64 b) {
    u64 r; asm("mul.rn.f32x2 %0, %1, %2;" : "=l"(r) : "l"(a), "l"(b)); return r;
}
__device__ __forceinline__ u64 bcast2(float x) {
    u64 r; asm("mov.b64 %0, {%1, %1};" : "=l"(r) : "f"(x)); return r;
}
__device__ __forceinline__ float2 unpk(u64 v) {
    float lo, hi; asm("mov.b64 {%0, %1}, %2;" : "=f"(lo), "=f"(hi) : "l"(v));
    return make_float2(lo, hi);
}

// ---------------------------------------------------------------------------
// Projection GEMM: Y[b,o,n] = bias[o] + sum_i W[o,i] * X[b,i,n]
// 64(o) x 64(n) tile, K-chunk 16, 256 threads, 4x4 micro-tile, f32x2 FMAs.
// ---------------------------------------------------------------------------
__global__ __launch_bounds__(256) void proj_kernel(
    const float* __restrict__ W, const float* __restrict__ bias,
    const float* __restrict__ X, float* __restrict__ Y)
{
    __shared__ float sW[16*PAD];   // [kk][oo]
    __shared__ float sX[16*PAD];   // [kk][nn]

    const int b  = blockIdx.z;
    const int o0 = blockIdx.y * 64;
    const int n0 = blockIdx.x * 64;
    const int t  = threadIdx.x;
    const int tx = t & 15;   // n group
    const int ty = t >> 4;   // o group

    const float* Xb = X + (size_t)b * DD * NN;
    u64 acc2[4][2];
#pragma unroll
    for (int i = 0; i < 4; i++) { acc2[i][0] = 0ull; acc2[i][1] = 0ull; }

    for (int k0 = 0; k0 < DD; k0 += 16) {
#pragma unroll
        for (int i = 0; i < 4; i++) {
            int idx = t + i * 256;            // 1024 elems
            int oo = idx >> 4, kk = idx & 15;
            sW[kk * PAD + oo] = W[(o0 + oo) * DD + k0 + kk];
        }
#pragma unroll
        for (int i = 0; i < 4; i++) {
            int idx = t + i * 256;
            int kk = idx >> 6, nn = idx & 63;
            sX[kk * PAD + nn] = Xb[(k0 + kk) * NN + n0 + nn];
        }
        __syncthreads();
#pragma unroll
        for (int kk = 0; kk < 16; kk++) {
            const float4 wv = *reinterpret_cast<const float4*>(&sW[kk * PAD + ty * 4]);
            const ulonglong2 xv = *reinterpret_cast<const ulonglong2*>(&sX[kk * PAD + tx * 4]);
            u64 w0 = bcast2(wv.x), w1 = bcast2(wv.y), w2 = bcast2(wv.z), w3 = bcast2(wv.w);
            ffma2(acc2[0][0], w0, xv.x); ffma2(acc2[0][1], w0, xv.y);
            ffma2(acc2[1][0], w1, xv.x); ffma2(acc2[1][1], w1, xv.y);
            ffma2(acc2[2][0], w2, xv.x); ffma2(acc2[2][1], w2, xv.y);
            ffma2(acc2[3][0], w3, xv.x); ffma2(acc2[3][1], w3, xv.y);
        }
        __syncthreads();
    }

    float* Yb = Y + (size_t)b * DD * NN;
#pragma unroll
    for (int i = 0; i < 4; i++) {
        int o = o0 + ty * 4 + i;
        float bv = bias[o];
        float2 a = unpk(acc2[i][0]);
        float2 c = unpk(acc2[i][1]);
        float4 outv = make_float4(a.x + bv, a.y + bv, c.x + bv, c.y + bv);
        *reinterpret_cast<float4*>(&Yb[o * NN + n0 + tx * 4]) = outv;
    }
}

// ---------------------------------------------------------------------------
// Flash attention fp32, register-blocked, f32x2 FMAs.
// Channel mapping: channel c = dd*NH + h (from reshape(B, d, H, N)).
// Block = (b, h, 64-query tile). 256 threads as 16(tx: key/dd grp) x 16(ty: q grp).
// ---------------------------------------------------------------------------
__global__ __launch_bounds__(256) void attn_kernel(const int* __restrict__ mask)
{
    extern __shared__ float sm[];
    float* sQT = sm;               // [dd][q]  64x64
    float* sKT = sQT + 64 * 64;    // [dd][k]  64x64
    float* sV  = sKT + 64 * 64;    // [m][dd]  64xPAD
    float* sP  = sV + 64 * PAD;    // [k][q]   64xPAD
    __shared__ int skm[64];
    __shared__ int sqm[64];

    const int b  = blockIdx.z;
    const int h  = blockIdx.y;
    const int q0 = blockIdx.x * 64;
    const int t  = threadIdx.x;
    const int tx = t & 15;   // key group (S) / dd group (O)
    const int ty = t >> 4;   // query group

    const float* Qb = g_q + (size_t)b * DD * NN;
    const float* Kb = g_k + (size_t)b * DD * NN;
    const float* Vb = g_v + (size_t)b * DD * NN;
    const int*   mb = mask + (size_t)b * NN;

#pragma unroll
    for (int i = 0; i < 16; i++) {
        int idx = t + i * 256;
        int dd = idx >> 6, q = idx & 63;
        sQT[dd * 64 + q] = Qb[(dd * NH + h) * NN + q0 + q];
    }
    if (t < 64) sqm[t] = mb[q0 + t];

    float mrow[4], lrow[4];
    u64 acc2[4][2];
#pragma unroll
    for (int i = 0; i < 4; i++) {
        mrow[i] = -INFINITY; lrow[i] = 0.f;
        acc2[i][0] = 0ull; acc2[i][1] = 0ull;
    }

    for (int k0 = 0; k0 < NN; k0 += 64) {
        __syncthreads();   // prev O GEMM done; sQT/sqm visible on first iter
#pragma unroll
        for (int i = 0; i < 16; i++) {
            int idx = t + i * 256;
            int dd = idx >> 6, m2 = idx & 63;
            sKT[dd * 64 + m2] = Kb[(dd * NH + h) * NN + k0 + m2];
        }
#pragma unroll
        for (int i = 0; i < 16; i++) {
            int idx = t + i * 256;
            int dd = idx >> 6, m2 = idx & 63;
            sV[m2 * PAD + dd] = Vb[(dd * NH + h) * NN + k0 + m2];
        }
        if (t < 64) skm[t] = mb[k0 + t];
        __syncthreads();

        // ---- S = Q K^T (packed pairs along k) ----
        u64 s2[4][2];
#pragma unroll
        for (int i = 0; i < 4; i++) { s2[i][0] = 0ull; s2[i][1] = 0ull; }
#pragma unroll 8
        for (int dd = 0; dd < 64; dd++) {
            const float4 qv = *reinterpret_cast<const float4*>(&sQT[dd * 64 + ty * 4]);
            const ulonglong2 kv = *reinterpret_cast<const ulonglong2*>(&sKT[dd * 64 + tx * 4]);
            u64 q0b = bcast2(qv.x), q1b = bcast2(qv.y), q2b = bcast2(qv.z), q3b = bcast2(qv.w);
            ffma2(s2[0][0], q0b, kv.x); ffma2(s2[0][1], q0b, kv.y);
            ffma2(s2[1][0], q1b, kv.x); ffma2(s2[1][1], q1b, kv.y);
            ffma2(s2[2][0], q2b, kv.x); ffma2(s2[2][1], q2b, kv.y);
            ffma2(s2[3][0], q3b, kv.x); ffma2(s2[3][1], q3b, kv.y);
        }

        // ---- unpack, mask, scale, online softmax ----
        float s[4][4];
#pragma unroll
        for (int i = 0; i < 4; i++) {
            float2 a = unpk(s2[i][0]); s[i][0] = a.x; s[i][1] = a.y;
            float2 c = unpk(s2[i][1]); s[i][2] = c.x; s[i][3] = c.y;
        }
        int km0 = skm[tx * 4 + 0], km1 = skm[tx * 4 + 1];
        int km2 = skm[tx * 4 + 2], km3 = skm[tx * 4 + 3];
        float corr[4];
#pragma unroll
        for (int i = 0; i < 4; i++) {
            int qmi = sqm[ty * 4 + i];
            s[i][0] = (qmi && km0) ? s[i][0] * 0.125f : -1e9f;
            s[i][1] = (qmi && km1) ? s[i][1] * 0.125f : -1e9f;
            s[i][2] = (qmi && km2) ? s[i][2] * 0.125f : -1e9f;
            s[i][3] = (qmi && km3) ? s[i][3] * 0.125f : -1e9f;
            float rmax = fmaxf(fmaxf(s[i][0], s[i][1]), fmaxf(s[i][2], s[i][3]));
            rmax = fmaxf(rmax, __shfl_xor_sync(0xffffffffu, rmax, 1));
            rmax = fmaxf(rmax, __shfl_xor_sync(0xffffffffu, rmax, 2));
            rmax = fmaxf(rmax, __shfl_xor_sync(0xffffffffu, rmax, 4));
            rmax = fmaxf(rmax, __shfl_xor_sync(0xffffffffu, rmax, 8));
            float mnew = fmaxf(mrow[i], rmax);
            corr[i] = __expf(mrow[i] - mnew);   // -inf first iter -> 0
            mrow[i] = mnew;
            float rsum = 0.f;
#pragma unroll
            for (int j = 0; j < 4; j++) {
                s[i][j] = __expf(s[i][j] - mnew);
                rsum += s[i][j];
            }
            rsum += __shfl_xor_sync(0xffffffffu, rsum, 1);
            rsum += __shfl_xor_sync(0xffffffffu, rsum, 2);
            rsum += __shfl_xor_sync(0xffffffffu, rsum, 4);
            rsum += __shfl_xor_sync(0xffffffffu, rsum, 8);
            lrow[i] = lrow[i] * corr[i] + rsum;
        }
        // rescale accumulator
#pragma unroll
        for (int i = 0; i < 4; i++) {
            u64 c2 = bcast2(corr[i]);
            acc2[i][0] = mul2(acc2[i][0], c2);
            acc2[i][1] = mul2(acc2[i][1], c2);
        }
        // stage P: sP[k][q]
#pragma unroll
        for (int j = 0; j < 4; j++) {
            float4 pv = make_float4(s[0][j], s[1][j], s[2][j], s[3][j]);
            *reinterpret_cast<float4*>(&sP[(tx * 4 + j) * PAD + ty * 4]) = pv;
        }
        __syncthreads();

        // ---- O += P V (packed pairs along dd) ----
#pragma unroll 8
        for (int m2 = 0; m2 < 64; m2++) {
            const float4 pv = *reinterpret_cast<const float4*>(&sP[m2 * PAD + ty * 4]);
            const ulonglong2 vv = *reinterpret_cast<const ulonglong2*>(&sV[m2 * PAD + tx * 4]);
            u64 p0 = bcast2(pv.x), p1 = bcast2(pv.y), p2 = bcast2(pv.z), p3 = bcast2(pv.w);
            ffma2(acc2[0][0], p0, vv.x); ffma2(acc2[0][1], p0, vv.y);
            ffma2(acc2[1][0], p1, vv.x); ffma2(acc2[1][1], p1, vv.y);
            ffma2(acc2[2][0], p2, vv.x); ffma2(acc2[2][1], p2, vv.y);
            ffma2(acc2[3][0], p3, vv.x); ffma2(acc2[3][1], p3, vv.y);
        }
    }

    // ---- epilogue: x[b, dd*NH+h, q0+q] = acc/l ----
    float* Xb = g_x + (size_t)b * DD * NN;
#pragma unroll
    for (int i = 0; i < 4; i++) {
        float inv = 1.f / lrow[i];
#pragma unroll
        for (int jp = 0; jp < 2; jp++) {
            float2 o = unpk(acc2[i][jp]);
            int dd0 = tx * 4 + jp * 2;
            Xb[((dd0 + 0) * NH + h) * NN + q0 + ty * 4 + i] = o.x * inv;
            Xb[((dd0 + 1) * NH + h) * NN + q0 + ty * 4 + i] = o.y * inv;
        }
    }
}

// ---------------------------------------------------------------------------
extern "C" void kernel_launch(void* const* d_in, const int* in_sizes, int n_in,
                              void* d_out, int out_size)
{
    const float* query = (const float*)d_in[0];
    const float* key_  = (const float*)d_in[1];
    const float* value = (const float*)d_in[2];
    const int*   mask  = (const int*)  d_in[3];
    const float* Wq = (const float*)d_in[4];
    const float* bq = (const float*)d_in[5];
    const float* Wk = (const float*)d_in[6];
    const float* bk = (const float*)d_in[7];
    const float* Wv = (const float*)d_in[8];
    const float* bv = (const float*)d_in[9];
    const float* Wm = (const float*)d_in[10];
    const float* bm = (const float*)d_in[11];
    float* out = (float*)d_out;

    float *q, *k, *v, *x;
    cudaGetSymbolAddress((void**)&q, g_q);
    cudaGetSymbolAddress((void**)&k, g_k);
    cudaGetSymbolAddress((void**)&v, g_v);
    cudaGetSymbolAddress((void**)&x, g_x);

    dim3 pgrid(NN / 64, DD / 64, BB);
    proj_kernel<<<pgrid, 256>>>(Wq, bq, query, q);
    proj_kernel<<<pgrid, 256>>>(Wk, bk, key_,  k);
    proj_kernel<<<pgrid, 256>>>(Wv, bv, value, v);

    size_t smem = (size_t)(2 * 64 * 64 + 2 * 64 * PAD) * sizeof(float);  // 67584
    cudaFuncSetAttribute(attn_kernel,
                         cudaFuncAttributeMaxDynamicSharedMemorySize, (int)smem);

    dim3 agrid(NN / 64, NH, BB);
    attn_kernel<<<agrid, 256, smem>>>(mask);

    proj_kernel<<<pgrid, 256>>>(Wm, bm, x, out);
}

// round 4
// speedup vs baseline: 6.8082x; 1.9771x over previous
#include <cuda_runtime.h>
#include <math.h>
#include <stdint.h>

#define BB 8
#define DD 256
#define NN 2048
#define NH 4
#define HD 64
#define PAD 68
#define QTILE 128
#define KTILE 64

typedef unsigned long long u64;
typedef unsigned int u32;

// Scratch. g_q/g_k TRANSPOSED per-head [b][h][tok][dd]; g_v/g_x natural [b][ch][tok].
__device__ float g_q[BB*DD*NN];
__device__ float g_k[BB*DD*NN];
__device__ float g_v[BB*DD*NN];
__device__ float g_x[BB*DD*NN];

// ---------------- packed f32x2 helpers ----------------
__device__ __forceinline__ void ffma2(u64& d, u64 a, u64 b) {
    asm("fma.rn.f32x2 %0, %1, %2, %3;" : "=l"(d) : "l"(a), "l"(b), "l"(d));
}
__device__ __forceinline__ u64 bcast2(float x) {
    u64 r; asm("mov.b64 %0, {%1, %1};" : "=l"(r) : "f"(x)); return r;
}
__device__ __forceinline__ float2 unpk(u64 v) {
    float lo, hi; asm("mov.b64 {%0, %1}, %2;" : "=f"(lo), "=f"(hi) : "l"(v));
    return make_float2(lo, hi);
}
__device__ __forceinline__ u32 f2tf32(float x) {
    u32 r; asm("cvt.rna.tf32.f32 %0, %1;" : "=r"(r) : "f"(x)); return r;
}
__device__ __forceinline__ void mma_tf32(float c[4], u32 a0, u32 a1, u32 a2, u32 a3,
                                         u32 b0, u32 b1) {
    asm volatile("mma.sync.aligned.m16n8k8.row.col.f32.tf32.tf32.f32 "
        "{%0,%1,%2,%3}, {%4,%5,%6,%7}, {%8,%9}, {%0,%1,%2,%3};"
        : "+f"(c[0]), "+f"(c[1]), "+f"(c[2]), "+f"(c[3])
        : "r"(a0), "r"(a1), "r"(a2), "r"(a3), "r"(b0), "r"(b1));
}

// ---------------------------------------------------------------------------
// Projection GEMM (fp32 exact, f32x2). TRANS=1 writes per-head [b][h][tok][dd].
// ---------------------------------------------------------------------------
template <int TRANS>
__global__ __launch_bounds__(256) void proj_kernel(
    const float* __restrict__ W, const float* __restrict__ bias,
    const float* __restrict__ X, float* __restrict__ Y)
{
    __shared__ float sW[16*PAD];
    __shared__ float sX[16*PAD];

    const int b  = blockIdx.z;
    const int o0 = blockIdx.y * 64;
    const int n0 = blockIdx.x * 64;
    const int t  = threadIdx.x;
    const int tx = t & 15;
    const int ty = t >> 4;

    const float* Xb = X + (size_t)b * DD * NN;
    u64 acc2[4][2];
#pragma unroll
    for (int i = 0; i < 4; i++) { acc2[i][0] = 0ull; acc2[i][1] = 0ull; }

    for (int k0 = 0; k0 < DD; k0 += 16) {
#pragma unroll
        for (int i = 0; i < 4; i++) {
            int idx = t + i * 256;
            int oo = idx >> 4, kk = idx & 15;
            sW[kk * PAD + oo] = W[(o0 + oo) * DD + k0 + kk];
        }
#pragma unroll
        for (int i = 0; i < 4; i++) {
            int idx = t + i * 256;
            int kk = idx >> 6, nn = idx & 63;
            sX[kk * PAD + nn] = Xb[(k0 + kk) * NN + n0 + nn];
        }
        __syncthreads();
#pragma unroll
        for (int kk = 0; kk < 16; kk++) {
            const float4 wv = *reinterpret_cast<const float4*>(&sW[kk * PAD + ty * 4]);
            const ulonglong2 xv = *reinterpret_cast<const ulonglong2*>(&sX[kk * PAD + tx * 4]);
            u64 w0 = bcast2(wv.x), w1 = bcast2(wv.y), w2 = bcast2(wv.z), w3 = bcast2(wv.w);
            ffma2(acc2[0][0], w0, xv.x); ffma2(acc2[0][1], w0, xv.y);
            ffma2(acc2[1][0], w1, xv.x); ffma2(acc2[1][1], w1, xv.y);
            ffma2(acc2[2][0], w2, xv.x); ffma2(acc2[2][1], w2, xv.y);
            ffma2(acc2[3][0], w3, xv.x); ffma2(acc2[3][1], w3, xv.y);
        }
        __syncthreads();
    }

#pragma unroll
    for (int i = 0; i < 4; i++) {
        int o = o0 + ty * 4 + i;
        float bv = bias[o];
        float2 a = unpk(acc2[i][0]);
        float2 c = unpk(acc2[i][1]);
        float v4[4] = {a.x + bv, a.y + bv, c.x + bv, c.y + bv};
        if (TRANS) {
            int dd = o >> 2, hh = o & 3;
            float* base = Y + (((size_t)b * NH + hh) * NN + n0 + tx * 4) * HD + dd;
#pragma unroll
            for (int j = 0; j < 4; j++) base[j * HD] = v4[j];
        } else {
            float* Yb = Y + (size_t)b * DD * NN;
            *reinterpret_cast<float4*>(&Yb[o * NN + n0 + tx * 4]) =
                make_float4(v4[0], v4[1], v4[2], v4[3]);
        }
    }
}

// ---------------------------------------------------------------------------
// mma.sync tf32 flash attention. CTA = (b, h, 128-query tile), 256 threads.
// Fragment-major SMEM layouts:
//   sQf/sPf: 64 frags (w*8+ks) of 132 u32: [lane*4 + slot], slot={a0,a1,a2,a3}
//   sKf/sVf: 64 frags (nb*8+ks) of 66 u32: [lane*2 + slot], slot={b0,b1}
// ---------------------------------------------------------------------------
__global__ __launch_bounds__(256, 2) void attn_mma(const int* __restrict__ mask)
{
    extern __shared__ float smf[];
    u32* sQf = (u32*)smf;            // 64*132
    u32* sKf = sQf + 64*132;         // 64*66
    u32* sVf = sKf + 64*66;          // 64*66
    u32* sPf = sVf + 64*66;          // 64*132
    int* skm = (int*)(sPf + 64*132); // 64

    const int t = threadIdx.x;
    const int w = t >> 5, lane = t & 31;
    const int gid = lane >> 2, tig = lane & 3;
    const int b = blockIdx.z, h = blockIdx.y;
    const int q0 = blockIdx.x * QTILE;

    // ---- Q tile -> A-fragment layout (fold 1/8 scale, tf32) ----
    const float* qb = g_q + (((size_t)b * NH + h) * NN + q0) * HD;
#pragma unroll
    for (int i = 0; i < 8; i++) {
        int idx4 = t + i * 256;
        int row = idx4 >> 4, dd4 = (idx4 & 15) * 4;
        float4 v = *(const float4*)(qb + row * HD + dd4);
        float vv[4] = {v.x, v.y, v.z, v.w};
        int wr = row >> 4, r16 = row & 15;
#pragma unroll
        for (int e = 0; e < 4; e++) {
            int dd = dd4 + e;
            int ks = dd >> 3, c = dd & 7;
            int slot = ((c >> 2) << 1) | (r16 >> 3);
            int lp = (r16 & 7) * 4 + (c & 3);
            sQf[(wr * 8 + ks) * 132 + lp * 4 + slot] = f2tf32(vv[e] * 0.125f);
        }
    }
    const int* mb_ = mask + (size_t)b * NN;
    const int qm0 = mb_[q0 + w * 16 + gid];
    const int qm1 = mb_[q0 + w * 16 + gid + 8];

    float oc[8][4];
#pragma unroll
    for (int nb = 0; nb < 8; nb++)
#pragma unroll
        for (int e = 0; e < 4; e++) oc[nb][e] = 0.f;
    float lsum0 = 0.f, lsum1 = 0.f;

    const float* kb0 = g_k + (((size_t)b * NH + h) * NN) * HD;
    const float* vb0 = g_v + ((size_t)b * DD + h) * NN;

    for (int k0 = 0; k0 < NN; k0 += KTILE) {
        __syncthreads();   // prev-iter PV reads of sKf/sVf done
        // ---- K tile -> B-frag layout ----
#pragma unroll
        for (int i = 0; i < 4; i++) {
            int idx4 = t + i * 256;
            int tok = idx4 >> 4, dd4 = (idx4 & 15) * 4;
            float4 v = *(const float4*)(kb0 + (size_t)(k0 + tok) * HD + dd4);
            float vv[4] = {v.x, v.y, v.z, v.w};
            int nb = tok >> 3, g2 = tok & 7;
#pragma unroll
            for (int e = 0; e < 4; e++) {
                int dd = dd4 + e;
                int ks = dd >> 3, c = dd & 7;
                sKf[(nb * 8 + ks) * 66 + (g2 * 4 + (c & 3)) * 2 + (c >> 2)] = f2tf32(vv[e]);
            }
        }
        // ---- V tile -> B-frag layout ----
#pragma unroll
        for (int i = 0; i < 4; i++) {
            int idx4 = t + i * 256;
            int dd = idx4 >> 4, tok4 = (idx4 & 15) * 4;
            float4 v = *(const float4*)(vb0 + (size_t)dd * NH * NN + k0 + tok4);
            float vv[4] = {v.x, v.y, v.z, v.w};
            int nb = dd >> 3, g2 = dd & 7;
#pragma unroll
            for (int e = 0; e < 4; e++) {
                int tok = tok4 + e;
                int kt = tok >> 3, c = tok & 7;
                sVf[(nb * 8 + kt) * 66 + (g2 * 4 + (c & 3)) * 2 + (c >> 2)] = f2tf32(vv[e]);
            }
        }
        if (t < KTILE) skm[t] = mb_[k0 + t];
        __syncthreads();

        // ---- S = Q K^T ----
        float sc[8][4];
#pragma unroll
        for (int nb = 0; nb < 8; nb++)
#pragma unroll
            for (int e = 0; e < 4; e++) sc[nb][e] = 0.f;
#pragma unroll
        for (int ks = 0; ks < 8; ks++) {
            uint4 a = *(const uint4*)&sQf[(w * 8 + ks) * 132 + lane * 4];
#pragma unroll
            for (int nb = 0; nb < 8; nb++) {
                uint2 bf = *(const uint2*)&sKf[(nb * 8 + ks) * 66 + lane * 2];
                mma_tf32(sc[nb], a.x, a.y, a.z, a.w, bf.x, bf.y);
            }
        }

        // ---- softmax (no-max), P -> A-frag layout (warp-private) ----
        __syncwarp();   // prev PV loads of sPf done
        float ps0 = 0.f, ps1 = 0.f;
#pragma unroll
        for (int nb = 0; nb < 8; nb++) {
            int j0 = nb * 8 + 2 * tig, j1 = j0 + 1;
            int km0_ = skm[j0], km1_ = skm[j1];
            float e0 = (qm0 && km0_) ? __expf(sc[nb][0]) : 0.f;
            float e1 = (qm0 && km1_) ? __expf(sc[nb][1]) : 0.f;
            float e2 = (qm1 && km0_) ? __expf(sc[nb][2]) : 0.f;
            float e3 = (qm1 && km1_) ? __expf(sc[nb][3]) : 0.f;
            ps0 += e0 + e1; ps1 += e2 + e3;
            u32* pb = sPf + (w * 8 + nb) * 132;
            int jb0 = 2 * tig;
            int l0 = gid * 4 + (jb0 & 3), s0 = (jb0 >> 2) << 1;
            pb[l0 * 4 + s0]     = f2tf32(e0);
            pb[l0 * 4 + s0 + 1] = f2tf32(e2);
            int jb1 = jb0 + 1;
            int l1 = gid * 4 + (jb1 & 3), s1 = (jb1 >> 2) << 1;
            pb[l1 * 4 + s1]     = f2tf32(e1);
            pb[l1 * 4 + s1 + 1] = f2tf32(e3);
        }
        ps0 += __shfl_xor_sync(~0u, ps0, 1); ps0 += __shfl_xor_sync(~0u, ps0, 2);
        ps1 += __shfl_xor_sync(~0u, ps1, 1); ps1 += __shfl_xor_sync(~0u, ps1, 2);
        lsum0 += ps0; lsum1 += ps1;
        __syncwarp();

        // ---- O += P V ----
#pragma unroll
        for (int kt = 0; kt < 8; kt++) {
            uint4 a = *(const uint4*)&sPf[(w * 8 + kt) * 132 + lane * 4];
#pragma unroll
            for (int nb = 0; nb < 8; nb++) {
                uint2 bf = *(const uint2*)&sVf[(nb * 8 + kt) * 66 + lane * 2];
                mma_tf32(oc[nb], a.x, a.y, a.z, a.w, bf.x, bf.y);
            }
        }
    }

    // ---- epilogue: x[b, dd*NH+h, tok] = O / l ----
    float inv0 = 1.f / lsum0, inv1 = 1.f / lsum1;
    float* xb = g_x + ((size_t)b * DD + h) * NN;
    int row0 = q0 + w * 16 + gid, row1 = row0 + 8;
#pragma unroll
    for (int nb = 0; nb < 8; nb++) {
        int dd0 = nb * 8 + 2 * tig;
        xb[(size_t)dd0 * NH * NN + row0]       = oc[nb][0] * inv0;
        xb[(size_t)(dd0 + 1) * NH * NN + row0] = oc[nb][1] * inv0;
        xb[(size_t)dd0 * NH * NN + row1]       = oc[nb][2] * inv1;
        xb[(size_t)(dd0 + 1) * NH * NN + row1] = oc[nb][3] * inv1;
    }
}

// ---------------------------------------------------------------------------
extern "C" void kernel_launch(void* const* d_in, const int* in_sizes, int n_in,
                              void* d_out, int out_size)
{
    const float* query = (const float*)d_in[0];
    const float* key_  = (const float*)d_in[1];
    const float* value = (const float*)d_in[2];
    const int*   mask  = (const int*)  d_in[3];
    const float* Wq = (const float*)d_in[4];
    const float* bq = (const float*)d_in[5];
    const float* Wk = (const float*)d_in[6];
    const float* bk = (const float*)d_in[7];
    const float* Wv = (const float*)d_in[8];
    const float* bv = (const float*)d_in[9];
    const float* Wm = (const float*)d_in[10];
    const float* bm = (const float*)d_in[11];
    float* out = (float*)d_out;

    float *q, *k, *v, *x;
    cudaGetSymbolAddress((void**)&q, g_q);
    cudaGetSymbolAddress((void**)&k, g_k);
    cudaGetSymbolAddress((void**)&v, g_v);
    cudaGetSymbolAddress((void**)&x, g_x);

    dim3 pgrid(NN / 64, DD / 64, BB);
    proj_kernel<1><<<pgrid, 256>>>(Wq, bq, query, q);
    proj_kernel<1><<<pgrid, 256>>>(Wk, bk, key_,  k);
    proj_kernel<0><<<pgrid, 256>>>(Wv, bv, value, v);

    const int asmem = (64*132 + 64*66 + 64*66 + 64*132) * 4 + 64 * 4;  // 101632
    cudaFuncSetAttribute(attn_mma, cudaFuncAttributeMaxDynamicSharedMemorySize, asmem);
    dim3 agrid(NN / QTILE, NH, BB);
    attn_mma<<<agrid, 256, asmem>>>(mask);

    proj_kernel<0><<<pgrid, 256>>>(Wm, bm, x, out);
}